// round 4
// baseline (speedup 1.0000x reference)
#include <cuda_runtime.h>
#include <math.h>
#include <stdint.h>

// ---------------- problem constants ----------------
#define BB 4
#define FFR 16
#define CC 3
#define HH 96
#define WW 128
#define PATP 8
#define HPP 12
#define WPP 16
#define NNS 192
#define TT (BB*FFR*NNS) // 12288
#define DIMM 512
#define NHEADS 8
#define DHH 64
#define NDEPTH 4
#define FFHID 2048
#define PATCH_K (PATP*PATP*CC) // 192
#define QSCALE 0.125f

// ---------------- device scratch ----------------
__device__ float g_x[TT*DIMM];
__device__ float g_y[TT*DIMM];
__device__ float g_qkv[(size_t)TT*3*DIMM];
__device__ float g_attn[TT*DIMM];
__device__ float g_h1[(size_t)TT*2*FFHID];
__device__ float g_patch[(size_t)TT*PATCH_K];
__device__ float g_fsin[FFR*DHH], g_fcos[FFR*DHH];
__device__ float g_isin[NNS*DHH], g_icos[NNS*DHH];

// ---------------- helpers ----------------
__device__ __forceinline__ float to_tf32(float x) {
    uint32_t u;
    asm("cvt.rna.tf32.f32 %0, %1;" : "=r"(u) : "f"(x));
    return __uint_as_float(u);
}

__device__ __forceinline__ void mma_tf32(float* c, const uint32_t* a, const uint32_t* b) {
    asm volatile(
        "mma.sync.aligned.m16n8k8.row.col.f32.tf32.tf32.f32 "
        "{%0,%1,%2,%3}, {%4,%5,%6,%7}, {%8,%9}, {%0,%1,%2,%3};"
        : "+f"(c[0]), "+f"(c[1]), "+f"(c[2]), "+f"(c[3])
        : "r"(a[0]), "r"(a[1]), "r"(a[2]), "r"(a[3]), "r"(b[0]), "r"(b[1]));
}

__device__ __forceinline__ float gelu_f(float g) {
    return 0.5f*g*(1.f + erff(g*0.70710678118654752f));
}

// ---------------- rope tables ----------------
__global__ void rope_frame_kernel() {
    int idx = blockIdx.x*blockDim.x + threadIdx.x;
    if (idx >= FFR*DHH) return;
    int f = idx / DHH, j = idx % DHH;
    int i = j & 31;
    float inv = expf(-((float)(2*i)/64.f) * logf(10000.f));
    float a = (float)f * inv;
    g_fsin[idx] = sinf(a);
    g_fcos[idx] = cosf(a);
}

__global__ void rope_image_kernel() {
    int idx = blockIdx.x*blockDim.x + threadIdx.x;
    if (idx >= NNS*DHH) return;
    int n = idx / DHH, j = idx % DHH;
    int half = j >> 1;
    int hp = n / WPP, wp = n % WPP;
    const float PI = 3.14159265358979323846f;
    const float LOG2_5 = 2.3219280948873623f;
    float ang;
    if (half < 16) {
        float sc = exp2f((float)half * (LOG2_5/15.f));
        float hl = -1.f + 2.f*(float)hp/11.f;
        ang = hl * sc * PI;
    } else {
        float sc = exp2f((float)(half-16) * (LOG2_5/15.f));
        float wl = -1.f + 2.f*(float)wp/15.f;
        ang = wl * sc * PI;
    }
    g_isin[idx] = sinf(ang);
    g_icos[idx] = cosf(ang);
}

// ---------------- patchify ----------------
__global__ void patchify_kernel(const float* __restrict__ video) {
    int idx = blockIdx.x*blockDim.x + threadIdx.x;
    if (idx >= TT*PATCH_K) return;
    int t = idx / PATCH_K, k = idx % PATCH_K;
    int n = t % NNS;
    int bf = t / NNS;
    int hp = n / WPP, wp = n % WPP;
    int p1 = k / (PATP*CC);
    int rem = k % (PATP*CC);
    int p2 = rem / CC;
    int c = rem % CC;
    g_patch[idx] = video[ (((size_t)(bf*CC + c))*HH + hp*PATP + p1)*WW + wp*PATP + p2 ];
}

// ---------------- TF32 GEMM: BM=128, BN template, 64x64 warp tiles ----------------
// C(MxN) = A(MxK_eff,lda) @ B(KxN) [+bias][+res]; GATED: A=a*gelu(g) from h1 layout
template<int BN, int NTHR, bool GATED>
__global__ __launch_bounds__(NTHR, 1) void tgemm(
    const float* __restrict__ A, const float* __restrict__ B,
    const float* __restrict__ bias, const float* __restrict__ res,
    float* __restrict__ C, int M, int N, int K, int lda)
{
    constexpr int APAD = 136;
    constexpr int BPAD = BN + 8;
    constexpr int ANUM = 512 / NTHR;          // A float4s per thread per k-tile
    constexpr int BNUM = (16*BN/4) / NTHR;    // B float4s per thread per k-tile
    constexpr int BQ = BN/4;                  // float4s per B row

    extern __shared__ float sm[];
    float* AsS = sm;                  // [2][16][APAD]
    float* BsS = sm + 2*16*APAD;      // [2][16][BPAD]

    int bx = blockIdx.x, by = blockIdx.y;
    int tid = threadIdx.x;
    int lane = tid & 31, warp = tid >> 5;
    int grp = lane >> 2, tig = lane & 3;
    int wm = (warp & 1) * 64;
    int wn = (warp >> 1) * 64;

    const float* Ap = A + (size_t)(by*128)*lda;
    const float* Bp = B + bx*BN;

    float acc[4][8][4];
    #pragma unroll
    for (int mi = 0; mi < 4; mi++)
        #pragma unroll
        for (int ni = 0; ni < 8; ni++)
            #pragma unroll
            for (int q = 0; q < 4; q++) acc[mi][ni][q] = 0.f;

    int KT = K >> 4;
    float4 pa[ANUM], pb[BNUM];

    // ---- preload kt=0 ----
    #pragma unroll
    for (int a = 0; a < ANUM; a++) {
        int i = tid + a*NTHR; int row = i >> 2; int c4 = (i & 3) << 2;
        const float* base = Ap + (size_t)row*lda + c4;
        if (GATED) {
            float4 av = *reinterpret_cast<const float4*>(base);
            float4 gv = *reinterpret_cast<const float4*>(base + FFHID);
            pa[a].x = av.x*gelu_f(gv.x); pa[a].y = av.y*gelu_f(gv.y);
            pa[a].z = av.z*gelu_f(gv.z); pa[a].w = av.w*gelu_f(gv.w);
        } else pa[a] = *reinterpret_cast<const float4*>(base);
    }
    #pragma unroll
    for (int bi = 0; bi < BNUM; bi++) {
        int i = tid + bi*NTHR; int row = i / BQ; int c4 = (i % BQ) << 2;
        pb[bi] = *reinterpret_cast<const float4*>(Bp + (size_t)row*N + c4);
    }
    // store buf 0
    #pragma unroll
    for (int a = 0; a < ANUM; a++) {
        int i = tid + a*NTHR; int row = i >> 2; int c4 = (i & 3) << 2;
        AsS[(c4+0)*APAD + row] = to_tf32(pa[a].x);
        AsS[(c4+1)*APAD + row] = to_tf32(pa[a].y);
        AsS[(c4+2)*APAD + row] = to_tf32(pa[a].z);
        AsS[(c4+3)*APAD + row] = to_tf32(pa[a].w);
    }
    #pragma unroll
    for (int bi = 0; bi < BNUM; bi++) {
        int i = tid + bi*NTHR; int row = i / BQ; int c4 = (i % BQ) << 2;
        float4 t;
        t.x = to_tf32(pb[bi].x); t.y = to_tf32(pb[bi].y);
        t.z = to_tf32(pb[bi].z); t.w = to_tf32(pb[bi].w);
        *reinterpret_cast<float4*>(&BsS[row*BPAD + c4]) = t;
    }
    __syncthreads();

    int buf = 0;
    for (int kt = 0; kt < KT; kt++) {
        if (kt + 1 < KT) {
            #pragma unroll
            for (int a = 0; a < ANUM; a++) {
                int i = tid + a*NTHR; int row = i >> 2; int c4 = (i & 3) << 2;
                const float* base = Ap + (size_t)row*lda + (kt+1)*16 + c4;
                if (GATED) {
                    float4 av = *reinterpret_cast<const float4*>(base);
                    float4 gv = *reinterpret_cast<const float4*>(base + FFHID);
                    pa[a].x = av.x*gelu_f(gv.x); pa[a].y = av.y*gelu_f(gv.y);
                    pa[a].z = av.z*gelu_f(gv.z); pa[a].w = av.w*gelu_f(gv.w);
                } else pa[a] = *reinterpret_cast<const float4*>(base);
            }
            #pragma unroll
            for (int bi = 0; bi < BNUM; bi++) {
                int i = tid + bi*NTHR; int row = i / BQ; int c4 = (i % BQ) << 2;
                pb[bi] = *reinterpret_cast<const float4*>(Bp + (size_t)((kt+1)*16 + row)*N + c4);
            }
        }
        const float* Ab = &AsS[buf*16*APAD];
        const float* Bb = &BsS[buf*16*BPAD];
        #pragma unroll
        for (int ks = 0; ks < 2; ks++) {
            int k0 = ks*8;
            uint32_t af[4][4], bf[8][2];
            #pragma unroll
            for (int mi = 0; mi < 4; mi++) {
                af[mi][0] = __float_as_uint(Ab[(k0+tig  )*APAD + wm+mi*16+grp  ]);
                af[mi][1] = __float_as_uint(Ab[(k0+tig  )*APAD + wm+mi*16+grp+8]);
                af[mi][2] = __float_as_uint(Ab[(k0+tig+4)*APAD + wm+mi*16+grp  ]);
                af[mi][3] = __float_as_uint(Ab[(k0+tig+4)*APAD + wm+mi*16+grp+8]);
            }
            #pragma unroll
            for (int ni = 0; ni < 8; ni++) {
                bf[ni][0] = __float_as_uint(Bb[(k0+tig  )*BPAD + wn+ni*8+grp]);
                bf[ni][1] = __float_as_uint(Bb[(k0+tig+4)*BPAD + wn+ni*8+grp]);
            }
            #pragma unroll
            for (int mi = 0; mi < 4; mi++)
                #pragma unroll
                for (int ni = 0; ni < 8; ni++)
                    mma_tf32(acc[mi][ni], af[mi], bf[ni]);
        }
        if (kt + 1 < KT) {
            int nb = buf ^ 1;
            float* Aw = &AsS[nb*16*APAD];
            float* Bw = &BsS[nb*16*BPAD];
            #pragma unroll
            for (int a = 0; a < ANUM; a++) {
                int i = tid + a*NTHR; int row = i >> 2; int c4 = (i & 3) << 2;
                Aw[(c4+0)*APAD + row] = to_tf32(pa[a].x);
                Aw[(c4+1)*APAD + row] = to_tf32(pa[a].y);
                Aw[(c4+2)*APAD + row] = to_tf32(pa[a].z);
                Aw[(c4+3)*APAD + row] = to_tf32(pa[a].w);
            }
            #pragma unroll
            for (int bi = 0; bi < BNUM; bi++) {
                int i = tid + bi*NTHR; int row = i / BQ; int c4 = (i % BQ) << 2;
                float4 t;
                t.x = to_tf32(pb[bi].x); t.y = to_tf32(pb[bi].y);
                t.z = to_tf32(pb[bi].z); t.w = to_tf32(pb[bi].w);
                *reinterpret_cast<float4*>(&Bw[row*BPAD + c4]) = t;
            }
            __syncthreads();
            buf = nb;
        }
    }

    // epilogue
    #pragma unroll
    for (int mi = 0; mi < 4; mi++) {
        #pragma unroll
        for (int ni = 0; ni < 8; ni++) {
            int row0 = by*128 + wm + mi*16 + grp;
            int row1 = row0 + 8;
            int col  = bx*BN + wn + ni*8 + 2*tig;
            float2 v0 = make_float2(acc[mi][ni][0], acc[mi][ni][1]);
            float2 v1 = make_float2(acc[mi][ni][2], acc[mi][ni][3]);
            if (bias) {
                float2 bb = *reinterpret_cast<const float2*>(bias + col);
                v0.x += bb.x; v0.y += bb.y; v1.x += bb.x; v1.y += bb.y;
            }
            if (res) {
                float2 r0 = *reinterpret_cast<const float2*>(res + (size_t)row0*N + col);
                float2 r1 = *reinterpret_cast<const float2*>(res + (size_t)row1*N + col);
                v0.x += r0.x; v0.y += r0.y; v1.x += r1.x; v1.y += r1.y;
            }
            *reinterpret_cast<float2*>(C + (size_t)row0*N + col) = v0;
            *reinterpret_cast<float2*>(C + (size_t)row1*N + col) = v1;
        }
    }
}

// ---------------- LayerNorm ----------------
__global__ __launch_bounds__(256) void ln_kernel(
    const float* __restrict__ x, const float* __restrict__ g,
    const float* __restrict__ b, float* __restrict__ y)
{
    int row = blockIdx.x;
    const float* xr = x + (size_t)row*DIMM;
    int tid = threadIdx.x;
    float v0 = xr[tid], v1 = xr[tid+256];
    __shared__ float red[8];
    float s = v0 + v1;
    #pragma unroll
    for (int o = 16; o > 0; o >>= 1) s += __shfl_xor_sync(0xffffffffu, s, o);
    if ((tid & 31) == 0) red[tid >> 5] = s;
    __syncthreads();
    float tot = 0.f;
    #pragma unroll
    for (int i = 0; i < 8; i++) tot += red[i];
    float mu = tot * (1.f/512.f);
    float d0 = v0 - mu, d1 = v1 - mu;
    __syncthreads();
    float vs = d0*d0 + d1*d1;
    #pragma unroll
    for (int o = 16; o > 0; o >>= 1) vs += __shfl_xor_sync(0xffffffffu, vs, o);
    if ((tid & 31) == 0) red[tid >> 5] = vs;
    __syncthreads();
    float vtot = 0.f;
    #pragma unroll
    for (int i = 0; i < 8; i++) vtot += red[i];
    float rstd = rsqrtf(vtot * (1.f/512.f) + 1e-5f);
    y[(size_t)row*DIMM + tid]       = d0*rstd*g[tid]       + b[tid];
    y[(size_t)row*DIMM + tid + 256] = d1*rstd*g[tid+256]   + b[tid+256];
}

// ---------------- temporal attention (fused, seq=16) ----------------
__global__ __launch_bounds__(256) void attn_time_kernel() {
    int n = blockIdx.x, h = blockIdx.y, b = blockIdx.z;
    __shared__ float qs[16*65], ks[16*65], vs[16*65], ps[16*17];
    int tid = threadIdx.x;
    for (int idx = tid; idx < 16*64; idx += 256) {
        int f = idx >> 6, d = idx & 63;
        size_t base = ((size_t)((b*FFR+f)*NNS + n))*(3*DIMM) + h*DHH + d;
        qs[f*65+d] = g_qkv[base] * QSCALE;
        ks[f*65+d] = g_qkv[base + DIMM];
        vs[f*65+d] = g_qkv[base + 2*DIMM];
    }
    __syncthreads();
    for (int p = tid; p < 16*32; p += 256) {
        int f = p >> 5, d = (p & 31) * 2;
        float s0 = g_fsin[f*64+d],   c0 = g_fcos[f*64+d];
        float s1 = g_fsin[f*64+d+1], c1 = g_fcos[f*64+d+1];
        float q0 = qs[f*65+d], q1 = qs[f*65+d+1];
        qs[f*65+d]   = q0*c0 - q1*s0;
        qs[f*65+d+1] = q1*c1 + q0*s1;
        float k0 = ks[f*65+d], k1 = ks[f*65+d+1];
        ks[f*65+d]   = k0*c0 - k1*s0;
        ks[f*65+d+1] = k1*c1 + k0*s1;
    }
    __syncthreads();
    {
        int i = tid >> 4, j = tid & 15;
        float acc = 0.f;
        #pragma unroll
        for (int d = 0; d < 64; d++) acc += qs[i*65+d]*ks[j*65+d];
        ps[i*17+j] = acc;
    }
    __syncthreads();
    if (tid < 16) {
        float m = -1e30f;
        #pragma unroll
        for (int j = 0; j < 16; j++) m = fmaxf(m, ps[tid*17+j]);
        float s = 0.f;
        #pragma unroll
        for (int j = 0; j < 16; j++) { float e = expf(ps[tid*17+j]-m); ps[tid*17+j]=e; s+=e; }
        float inv = 1.f/s;
        #pragma unroll
        for (int j = 0; j < 16; j++) ps[tid*17+j] *= inv;
    }
    __syncthreads();
    #pragma unroll
    for (int r = 0; r < 4; r++) {
        int idx = tid + r*256;
        int i = idx >> 6, d = idx & 63;
        float acc = 0.f;
        #pragma unroll
        for (int j = 0; j < 16; j++) acc += ps[i*17+j]*vs[j*65+d];
        g_attn[ ((size_t)((b*FFR+i)*NNS + n))*DIMM + h*DHH + d ] = acc;
    }
}

// ---------------- fused spatial attention (one block per (b,h,f)) ----------------
// smem: K[192][65], V[192][72], Q[32][65], S[32][193]
#define SA_KS   0
#define SA_VS   (192*65)
#define SA_QS   (SA_VS + 192*72)
#define SA_SS   (SA_QS + 32*65)
#define SA_TOT  (SA_SS + 32*193)

__global__ __launch_bounds__(256) void attn_space_kernel() {
    extern __shared__ float sa[];
    float* Ks = sa + SA_KS;
    float* Vs = sa + SA_VS;
    float* Qs = sa + SA_QS;
    float* Ss = sa + SA_SS;
    int seq = blockIdx.x;
    int f = seq & 15, h = (seq >> 4) & 7, b = seq >> 7;
    int tid = threadIdx.x;
    size_t tokbase = ((size_t)((b*FFR+f)*NNS))*(3*DIMM) + h*DHH;

    for (int idx = tid; idx < 192*64; idx += 256) {
        int r = idx >> 6, d = idx & 63;
        size_t base = tokbase + (size_t)r*(3*DIMM) + d;
        Ks[r*65+d] = g_qkv[base + DIMM];
        Vs[r*72+d] = g_qkv[base + 2*DIMM];
    }
    __syncthreads();
    for (int p = tid; p < 192*32; p += 256) {
        int r = p >> 5, d = (p & 31) * 2;
        float s0 = g_isin[r*64+d],   c0 = g_icos[r*64+d];
        float s1 = g_isin[r*64+d+1], c1 = g_icos[r*64+d+1];
        float k0 = Ks[r*65+d], k1 = Ks[r*65+d+1];
        Ks[r*65+d]   = k0*c0 - k1*s0;
        Ks[r*65+d+1] = k1*c1 + k0*s1;
    }
    __syncthreads();

    for (int qt = 0; qt < 6; qt++) {
        for (int idx = tid; idx < 32*64; idx += 256) {
            int r = idx >> 6, d = idx & 63;
            int n = qt*32 + r;
            Qs[r*65+d] = g_qkv[tokbase + (size_t)n*(3*DIMM) + d] * QSCALE;
        }
        __syncthreads();
        for (int p = tid; p < 32*32; p += 256) {
            int r = p >> 5, d = (p & 31) * 2;
            int n = qt*32 + r;
            float s0 = g_isin[n*64+d],   c0 = g_icos[n*64+d];
            float s1 = g_isin[n*64+d+1], c1 = g_icos[n*64+d+1];
            float q0 = Qs[r*65+d], q1 = Qs[r*65+d+1];
            Qs[r*65+d]   = q0*c0 - q1*s0;
            Qs[r*65+d+1] = q1*c1 + q0*s1;
        }
        __syncthreads();
        // S = Q K^T  (32 x 192)
        {
            int i0 = (tid >> 5) * 4, j = tid & 31;
            float acc[4][6];
            #pragma unroll
            for (int r = 0; r < 4; r++)
                #pragma unroll
                for (int jc = 0; jc < 6; jc++) acc[r][jc] = 0.f;
            for (int d = 0; d < 64; d++) {
                float q0 = Qs[(i0+0)*65+d];
                float q1 = Qs[(i0+1)*65+d];
                float q2 = Qs[(i0+2)*65+d];
                float q3 = Qs[(i0+3)*65+d];
                #pragma unroll
                for (int jc = 0; jc < 6; jc++) {
                    float kv = Ks[(jc*32+j)*65+d];
                    acc[0][jc] = fmaf(q0, kv, acc[0][jc]);
                    acc[1][jc] = fmaf(q1, kv, acc[1][jc]);
                    acc[2][jc] = fmaf(q2, kv, acc[2][jc]);
                    acc[3][jc] = fmaf(q3, kv, acc[3][jc]);
                }
            }
            #pragma unroll
            for (int r = 0; r < 4; r++)
                #pragma unroll
                for (int jc = 0; jc < 6; jc++)
                    Ss[(i0+r)*193 + jc*32 + j] = acc[r][jc];
        }
        __syncthreads();
        // softmax rows (8 warps x 4 rows)
        {
            int w = tid >> 5, ln = tid & 31;
            #pragma unroll
            for (int rr = 0; rr < 4; rr++) {
                int row = w*4 + rr;
                float v[6];
                float m = -1e30f;
                #pragma unroll
                for (int t = 0; t < 6; t++) { v[t] = Ss[row*193 + ln + t*32]; m = fmaxf(m, v[t]); }
                #pragma unroll
                for (int o = 16; o > 0; o >>= 1) m = fmaxf(m, __shfl_xor_sync(0xffffffffu, m, o));
                float s = 0.f;
                #pragma unroll
                for (int t = 0; t < 6; t++) { v[t] = expf(v[t]-m); s += v[t]; }
                #pragma unroll
                for (int o = 16; o > 0; o >>= 1) s += __shfl_xor_sync(0xffffffffu, s, o);
                float inv = 1.f/s;
                #pragma unroll
                for (int t = 0; t < 6; t++) Ss[row*193 + ln + t*32] = v[t]*inv;
            }
        }
        __syncthreads();
        // O = P V  (32 x 64)
        {
            int r = tid >> 3, c0 = (tid & 7) * 8;
            float o[8] = {0.f,0.f,0.f,0.f,0.f,0.f,0.f,0.f};
            for (int j = 0; j < 192; j++) {
                float p = Ss[r*193 + j];
                float4 v0 = *reinterpret_cast<const float4*>(&Vs[j*72 + c0]);
                float4 v1 = *reinterpret_cast<const float4*>(&Vs[j*72 + c0 + 4]);
                o[0] = fmaf(p, v0.x, o[0]); o[1] = fmaf(p, v0.y, o[1]);
                o[2] = fmaf(p, v0.z, o[2]); o[3] = fmaf(p, v0.w, o[3]);
                o[4] = fmaf(p, v1.x, o[4]); o[5] = fmaf(p, v1.y, o[5]);
                o[6] = fmaf(p, v1.z, o[6]); o[7] = fmaf(p, v1.w, o[7]);
            }
            int n = qt*32 + r;
            float* dst = &g_attn[((size_t)((b*FFR+f)*NNS + n))*DIMM + h*DHH + c0];
            float4 w0 = make_float4(o[0], o[1], o[2], o[3]);
            float4 w1 = make_float4(o[4], o[5], o[6], o[7]);
            *reinterpret_cast<float4*>(dst)   = w0;
            *reinterpret_cast<float4*>(dst+4) = w1;
        }
        __syncthreads();
    }
}

// ---------------- host orchestration ----------------
extern "C" void kernel_launch(void* const* d_in, const int* in_sizes, int n_in,
                              void* d_out, int out_size) {
    const float* video   = (const float*)d_in[0];
    const float* patch_w = (const float*)d_in[1];
    const float* patch_b = (const float*)d_in[2];
    const float* ln_t_g  = (const float*)d_in[3];
    const float* ln_t_b  = (const float*)d_in[4];
    const float* ln_s_g  = (const float*)d_in[5];
    const float* ln_s_b  = (const float*)d_in[6];
    const float* ln_f_g  = (const float*)d_in[7];
    const float* ln_f_b  = (const float*)d_in[8];
    const float* qkv_t   = (const float*)d_in[9];
    const float* out_t_w = (const float*)d_in[10];
    const float* out_t_b = (const float*)d_in[11];
    const float* qkv_s   = (const float*)d_in[12];
    const float* out_s_w = (const float*)d_in[13];
    const float* out_s_b = (const float*)d_in[14];
    const float* ff_w1   = (const float*)d_in[15];
    const float* ff_b1   = (const float*)d_in[16];
    const float* ff_w2   = (const float*)d_in[17];
    const float* ff_b2   = (const float*)d_in[18];

    float *px, *py, *pqkv, *pattn, *ph1, *ppatch;
    cudaGetSymbolAddress((void**)&px,     g_x);
    cudaGetSymbolAddress((void**)&py,     g_y);
    cudaGetSymbolAddress((void**)&pqkv,   g_qkv);
    cudaGetSymbolAddress((void**)&pattn,  g_attn);
    cudaGetSymbolAddress((void**)&ph1,    g_h1);
    cudaGetSymbolAddress((void**)&ppatch, g_patch);

    const int SM128 = (2*16*136 + 2*16*136)*4;   // 34816 B
    const int SM256 = (2*16*136 + 2*16*264)*4;   // 51200 B
    const int SMATT = SA_TOT*4;                  // 138240 B

    static bool attr_done = false;
    if (!attr_done) {
        cudaFuncSetAttribute(tgemm<128,128,false>, cudaFuncAttributeMaxDynamicSharedMemorySize, SM128);
        cudaFuncSetAttribute(tgemm<128,128,true>,  cudaFuncAttributeMaxDynamicSharedMemorySize, SM128);
        cudaFuncSetAttribute(tgemm<256,256,false>, cudaFuncAttributeMaxDynamicSharedMemorySize, SM256);
        cudaFuncSetAttribute(attn_space_kernel,    cudaFuncAttributeMaxDynamicSharedMemorySize, SMATT);
        attr_done = true;
    }

    rope_frame_kernel<<<1, 1024>>>();
    rope_image_kernel<<<(NNS*DHH+255)/256, 256>>>();
    patchify_kernel<<<(TT*PATCH_K+255)/256, 256>>>(video);

    // x = patch @ patch_w + patch_b   (N=512, K=192)
    tgemm<128,128,false><<<dim3(DIMM/128, TT/128), 128, SM128>>>(
        ppatch, patch_w, patch_b, nullptr, px, TT, DIMM, PATCH_K, PATCH_K);

    for (int l = 0; l < NDEPTH; l++) {
        // ---- temporal attention ----
        ln_kernel<<<TT, 256>>>(px, ln_t_g + l*DIMM, ln_t_b + l*DIMM, py);
        tgemm<256,256,false><<<dim3(3*DIMM/256, TT/128), 256, SM256>>>(
            py, qkv_t + (size_t)l*DIMM*3*DIMM, nullptr, nullptr, pqkv, TT, 3*DIMM, DIMM, DIMM);
        attn_time_kernel<<<dim3(NNS, NHEADS, BB), 256>>>();
        tgemm<128,128,false><<<dim3(DIMM/128, TT/128), 128, SM128>>>(
            pattn, out_t_w + (size_t)l*DIMM*DIMM, out_t_b + l*DIMM, px, px, TT, DIMM, DIMM, DIMM);
        // ---- spatial attention ----
        ln_kernel<<<TT, 256>>>(px, ln_s_g + l*DIMM, ln_s_b + l*DIMM, py);
        tgemm<256,256,false><<<dim3(3*DIMM/256, TT/128), 256, SM256>>>(
            py, qkv_s + (size_t)l*DIMM*3*DIMM, nullptr, nullptr, pqkv, TT, 3*DIMM, DIMM, DIMM);
        attn_space_kernel<<<BB*NHEADS*FFR, 256, SMATT>>>();
        tgemm<128,128,false><<<dim3(DIMM/128, TT/128), 128, SM128>>>(
            pattn, out_s_w + (size_t)l*DIMM*DIMM, out_s_b + l*DIMM, px, px, TT, DIMM, DIMM, DIMM);
        // ---- FFN (gated GELU fused into ff2's A load) ----
        ln_kernel<<<TT, 256>>>(px, ln_f_g + l*DIMM, ln_f_b + l*DIMM, py);
        tgemm<256,256,false><<<dim3(2*FFHID/256, TT/128), 256, SM256>>>(
            py, ff_w1 + (size_t)l*DIMM*2*FFHID, ff_b1 + (size_t)l*2*FFHID, nullptr, ph1,
            TT, 2*FFHID, DIMM, DIMM);
        float* cdst = (l == NDEPTH-1) ? (float*)d_out : px;
        tgemm<128,128,true><<<dim3(DIMM/128, TT/128), 128, SM128>>>(
            ph1, ff_w2 + (size_t)l*FFHID*DIMM, ff_b2 + l*DIMM, px, cdst,
            TT, DIMM, FFHID, 2*FFHID);
    }
}

// round 5
// speedup vs baseline: 1.1799x; 1.1799x over previous
#include <cuda_runtime.h>
#include <math.h>
#include <stdint.h>

// ---------------- problem constants ----------------
#define BB 4
#define FFR 16
#define CC 3
#define HH 96
#define WW 128
#define PATP 8
#define HPP 12
#define WPP 16
#define NNS 192
#define TT (BB*FFR*NNS) // 12288
#define DIMM 512
#define NHEADS 8
#define DHH 64
#define NDEPTH 4
#define FFHID 2048
#define PATCH_K (PATP*PATP*CC) // 192
#define QSCALE 0.125f

// ---------------- device scratch ----------------
__device__ float g_x[TT*DIMM];
__device__ float g_y[TT*DIMM];
__device__ float g_qkv[(size_t)TT*3*DIMM];
__device__ float g_attn[TT*DIMM];
__device__ float g_h1[(size_t)TT*2*FFHID];
__device__ float g_gate[(size_t)TT*FFHID];
__device__ float g_patch[(size_t)TT*PATCH_K];
__device__ float g_fsin[FFR*DHH], g_fcos[FFR*DHH];
__device__ float g_isin[NNS*DHH], g_icos[NNS*DHH];

// ---------------- helpers ----------------
__device__ __forceinline__ uint32_t cvt_tf32(float x) {
    uint32_t u;
    asm("cvt.rna.tf32.f32 %0, %1;" : "=r"(u) : "f"(x));
    return u;
}

__device__ __forceinline__ void mma_tf32(float* c, const uint32_t* a, const uint32_t* b) {
    asm volatile(
        "mma.sync.aligned.m16n8k8.row.col.f32.tf32.tf32.f32 "
        "{%0,%1,%2,%3}, {%4,%5,%6,%7}, {%8,%9}, {%0,%1,%2,%3};"
        : "+f"(c[0]), "+f"(c[1]), "+f"(c[2]), "+f"(c[3])
        : "r"(a[0]), "r"(a[1]), "r"(a[2]), "r"(a[3]), "r"(b[0]), "r"(b[1]));
}

__device__ __forceinline__ void cpa16(uint32_t dst, const float* src) {
    asm volatile("cp.async.cg.shared.global [%0], [%1], 16;" :: "r"(dst), "l"(src));
}
#define CP_COMMIT() asm volatile("cp.async.commit_group;")
#define CP_WAIT(n)  asm volatile("cp.async.wait_group %0;" :: "n"(n))

__device__ __forceinline__ float gelu_f(float g) {
    return 0.5f*g*(1.f + erff(g*0.70710678118654752f));
}

// ---------------- rope tables ----------------
__global__ void rope_frame_kernel() {
    int idx = blockIdx.x*blockDim.x + threadIdx.x;
    if (idx >= FFR*DHH) return;
    int f = idx / DHH, j = idx % DHH;
    int i = j & 31;
    float inv = expf(-((float)(2*i)/64.f) * logf(10000.f));
    float a = (float)f * inv;
    g_fsin[idx] = sinf(a);
    g_fcos[idx] = cosf(a);
}

__global__ void rope_image_kernel() {
    int idx = blockIdx.x*blockDim.x + threadIdx.x;
    if (idx >= NNS*DHH) return;
    int n = idx / DHH, j = idx % DHH;
    int half = j >> 1;
    int hp = n / WPP, wp = n % WPP;
    const float PI = 3.14159265358979323846f;
    const float LOG2_5 = 2.3219280948873623f;
    float ang;
    if (half < 16) {
        float sc = exp2f((float)half * (LOG2_5/15.f));
        float hl = -1.f + 2.f*(float)hp/11.f;
        ang = hl * sc * PI;
    } else {
        float sc = exp2f((float)(half-16) * (LOG2_5/15.f));
        float wl = -1.f + 2.f*(float)wp/15.f;
        ang = wl * sc * PI;
    }
    g_isin[idx] = sinf(ang);
    g_icos[idx] = cosf(ang);
}

// ---------------- patchify ----------------
__global__ void patchify_kernel(const float* __restrict__ video) {
    int idx = blockIdx.x*blockDim.x + threadIdx.x;
    if (idx >= TT*PATCH_K) return;
    int t = idx / PATCH_K, k = idx % PATCH_K;
    int n = t % NNS;
    int bf = t / NNS;
    int hp = n / WPP, wp = n % WPP;
    int p1 = k / (PATP*CC);
    int rem = k % (PATP*CC);
    int p2 = rem / CC;
    int c = rem % CC;
    g_patch[idx] = video[ (((size_t)(bf*CC + c))*HH + hp*PATP + p1)*WW + wp*PATP + p2 ];
}

// ---------------- TF32 GEMM, cp.async 3-stage, cvt at fragment load ----------------
// C(MxN) = A(MxK,lda) @ B(KxN) [+bias][+res].  BM=128, BN in {128,256}, 256 thr.
template<int BN>
__global__ __launch_bounds__(256, 1) void tgemm(
    const float* __restrict__ A, const float* __restrict__ B,
    const float* __restrict__ bias, const float* __restrict__ res,
    float* __restrict__ C, int M, int N, int K, int lda)
{
    constexpr int NTHR = 256;
    constexpr int APAD = 20;               // 16 k + 4 pad (bank-safe, 16B aligned)
    constexpr int BROW = BN + 8;
    constexpr int ASZ = 128*APAD;          // floats per stage
    constexpr int BSZ = 16*BROW;
    constexpr int NI = BN/32;              // n-tiles per warp (4 or 8)
    constexpr int BNUM = (16*BN/4)/NTHR;   // B float4s per thread
    constexpr int WNS = BN/4;              // warp n-stride (32 or 64)

    extern __shared__ float sm[];
    float* Asm = sm;              // [3][128][APAD]  (m-major)
    float* Bsm = sm + 3*ASZ;      // [3][16][BROW]   (k-major)

    int bx = blockIdx.x, by = blockIdx.y;
    int tid = threadIdx.x;
    int lane = tid & 31, warp = tid >> 5;
    int grp = lane >> 2, tig = lane & 3;
    int wm = (warp & 1) * 64;
    int wn = (warp >> 1) * WNS;

    const float* Ap = A + (size_t)(by*128)*lda;
    const float* Bp = B + bx*BN;

    float acc[4][NI][4];
    #pragma unroll
    for (int mi = 0; mi < 4; mi++)
        #pragma unroll
        for (int ni = 0; ni < NI; ni++)
            #pragma unroll
            for (int q = 0; q < 4; q++) acc[mi][ni][q] = 0.f;

    int KT = K >> 4;

    auto issue_stage = [&](int kt, int st) {
        #pragma unroll
        for (int a = 0; a < 2; a++) {
            int i = tid + a*NTHR;               // 0..511
            int row = i >> 2, c4 = (i & 3) << 2;
            uint32_t dst = (uint32_t)__cvta_generic_to_shared(&Asm[st*ASZ + row*APAD + c4]);
            cpa16(dst, Ap + (size_t)row*lda + kt*16 + c4);
        }
        #pragma unroll
        for (int bi = 0; bi < BNUM; bi++) {
            int i = tid + bi*NTHR;
            int row = i / (BN/4), c4 = (i % (BN/4)) << 2;
            uint32_t dst = (uint32_t)__cvta_generic_to_shared(&Bsm[st*BSZ + row*BROW + c4]);
            cpa16(dst, Bp + (size_t)(kt*16 + row)*N + c4);
        }
        CP_COMMIT();
    };

    // prologue: stages 0,1 (all K here have KT>=2)
    issue_stage(0, 0);
    issue_stage(1, 1);
    CP_WAIT(1);
    __syncthreads();

    for (int kt = 0; kt < KT; kt++) {
        int buf = kt % 3;
        bool more = (kt + 2 < KT);
        if (more) issue_stage(kt+2, (kt+2) % 3);

        const float* Ab = &Asm[buf*ASZ];
        const float* Bb = &Bsm[buf*BSZ];
        #pragma unroll
        for (int ks = 0; ks < 2; ks++) {
            int k0 = ks*8;
            uint32_t af[4][4], bf[NI][2];
            #pragma unroll
            for (int mi = 0; mi < 4; mi++) {
                int m = wm + mi*16 + grp;
                af[mi][0] = cvt_tf32(Ab[(size_t)m*APAD     + k0+tig  ]);
                af[mi][1] = cvt_tf32(Ab[(size_t)(m+8)*APAD + k0+tig  ]);
                af[mi][2] = cvt_tf32(Ab[(size_t)m*APAD     + k0+tig+4]);
                af[mi][3] = cvt_tf32(Ab[(size_t)(m+8)*APAD + k0+tig+4]);
            }
            #pragma unroll
            for (int ni = 0; ni < NI; ni++) {
                bf[ni][0] = cvt_tf32(Bb[(k0+tig  )*BROW + wn+ni*8+grp]);
                bf[ni][1] = cvt_tf32(Bb[(k0+tig+4)*BROW + wn+ni*8+grp]);
            }
            #pragma unroll
            for (int mi = 0; mi < 4; mi++)
                #pragma unroll
                for (int ni = 0; ni < NI; ni++)
                    mma_tf32(acc[mi][ni], af[mi], bf[ni]);
        }

        if (kt + 1 < KT) {
            if (more) { CP_WAIT(1); } else { CP_WAIT(0); }
            __syncthreads();
        }
    }

    // epilogue
    #pragma unroll
    for (int mi = 0; mi < 4; mi++) {
        #pragma unroll
        for (int ni = 0; ni < NI; ni++) {
            int row0 = by*128 + wm + mi*16 + grp;
            int row1 = row0 + 8;
            int col  = bx*BN + wn + ni*8 + 2*tig;
            float2 v0 = make_float2(acc[mi][ni][0], acc[mi][ni][1]);
            float2 v1 = make_float2(acc[mi][ni][2], acc[mi][ni][3]);
            if (bias) {
                float2 bb = *reinterpret_cast<const float2*>(bias + col);
                v0.x += bb.x; v0.y += bb.y; v1.x += bb.x; v1.y += bb.y;
            }
            if (res) {
                float2 r0 = *reinterpret_cast<const float2*>(res + (size_t)row0*N + col);
                float2 r1 = *reinterpret_cast<const float2*>(res + (size_t)row1*N + col);
                v0.x += r0.x; v0.y += r0.y; v1.x += r1.x; v1.y += r1.y;
            }
            *reinterpret_cast<float2*>(C + (size_t)row0*N + col) = v0;
            *reinterpret_cast<float2*>(C + (size_t)row1*N + col) = v1;
        }
    }
}

// ---------------- LayerNorm ----------------
__global__ __launch_bounds__(256) void ln_kernel(
    const float* __restrict__ x, const float* __restrict__ g,
    const float* __restrict__ b, float* __restrict__ y)
{
    int row = blockIdx.x;
    const float* xr = x + (size_t)row*DIMM;
    int tid = threadIdx.x;
    float v0 = xr[tid], v1 = xr[tid+256];
    __shared__ float red[8];
    float s = v0 + v1;
    #pragma unroll
    for (int o = 16; o > 0; o >>= 1) s += __shfl_xor_sync(0xffffffffu, s, o);
    if ((tid & 31) == 0) red[tid >> 5] = s;
    __syncthreads();
    float tot = 0.f;
    #pragma unroll
    for (int i = 0; i < 8; i++) tot += red[i];
    float mu = tot * (1.f/512.f);
    float d0 = v0 - mu, d1 = v1 - mu;
    __syncthreads();
    float vs = d0*d0 + d1*d1;
    #pragma unroll
    for (int o = 16; o > 0; o >>= 1) vs += __shfl_xor_sync(0xffffffffu, vs, o);
    if ((tid & 31) == 0) red[tid >> 5] = vs;
    __syncthreads();
    float vtot = 0.f;
    #pragma unroll
    for (int i = 0; i < 8; i++) vtot += red[i];
    float rstd = rsqrtf(vtot * (1.f/512.f) + 1e-5f);
    y[(size_t)row*DIMM + tid]       = d0*rstd*g[tid]       + b[tid];
    y[(size_t)row*DIMM + tid + 256] = d1*rstd*g[tid+256]   + b[tid+256];
}

// ---------------- temporal attention (fused, seq=16) ----------------
__global__ __launch_bounds__(256) void attn_time_kernel() {
    int n = blockIdx.x, h = blockIdx.y, b = blockIdx.z;
    __shared__ float qs[16*65], ks[16*65], vs[16*65], ps[16*17];
    int tid = threadIdx.x;
    for (int idx = tid; idx < 16*64; idx += 256) {
        int f = idx >> 6, d = idx & 63;
        size_t base = ((size_t)((b*FFR+f)*NNS + n))*(3*DIMM) + h*DHH + d;
        qs[f*65+d] = g_qkv[base] * QSCALE;
        ks[f*65+d] = g_qkv[base + DIMM];
        vs[f*65+d] = g_qkv[base + 2*DIMM];
    }
    __syncthreads();
    for (int p = tid; p < 16*32; p += 256) {
        int f = p >> 5, d = (p & 31) * 2;
        float s0 = g_fsin[f*64+d],   c0 = g_fcos[f*64+d];
        float s1 = g_fsin[f*64+d+1], c1 = g_fcos[f*64+d+1];
        float q0 = qs[f*65+d], q1 = qs[f*65+d+1];
        qs[f*65+d]   = q0*c0 - q1*s0;
        qs[f*65+d+1] = q1*c1 + q0*s1;
        float k0 = ks[f*65+d], k1 = ks[f*65+d+1];
        ks[f*65+d]   = k0*c0 - k1*s0;
        ks[f*65+d+1] = k1*c1 + k0*s1;
    }
    __syncthreads();
    {
        int i = tid >> 4, j = tid & 15;
        float acc = 0.f;
        #pragma unroll
        for (int d = 0; d < 64; d++) acc += qs[i*65+d]*ks[j*65+d];
        ps[i*17+j] = acc;
    }
    __syncthreads();
    if (tid < 16) {
        float m = -1e30f;
        #pragma unroll
        for (int j = 0; j < 16; j++) m = fmaxf(m, ps[tid*17+j]);
        float s = 0.f;
        #pragma unroll
        for (int j = 0; j < 16; j++) { float e = expf(ps[tid*17+j]-m); ps[tid*17+j]=e; s+=e; }
        float inv = 1.f/s;
        #pragma unroll
        for (int j = 0; j < 16; j++) ps[tid*17+j] *= inv;
    }
    __syncthreads();
    #pragma unroll
    for (int r = 0; r < 4; r++) {
        int idx = tid + r*256;
        int i = idx >> 6, d = idx & 63;
        float acc = 0.f;
        #pragma unroll
        for (int j = 0; j < 16; j++) acc += ps[i*17+j]*vs[j*65+d];
        g_attn[ ((size_t)((b*FFR+i)*NNS + n))*DIMM + h*DHH + d ] = acc;
    }
}

// ---------------- fused spatial attention v2 ----------------
// grid (6 qtiles, 512 seqs), 256 threads, ~42.6 KB static smem
__global__ __launch_bounds__(256) void attn_space_kernel() {
    __shared__ float Qs[32*65];
    __shared__ float Ss[32*200];
    __shared__ float KVc[32*68];
    int qt = blockIdx.x;
    int seq = blockIdx.y;
    int f = seq & 15, h = (seq >> 4) & 7, b = seq >> 7;
    int tid = threadIdx.x;
    size_t tokbase = ((size_t)((b*FFR+f)*NNS))*(3*DIMM) + h*DHH;

    // load Q tile with rope + scale
    for (int p = tid; p < 32*32; p += 256) {
        int r = p >> 5, d = (p & 31) * 2;
        int n = qt*32 + r;
        float2 q = *reinterpret_cast<const float2*>(&g_qkv[tokbase + (size_t)n*(3*DIMM) + d]);
        float s0 = g_isin[n*64+d],   c0 = g_icos[n*64+d];
        float s1 = g_isin[n*64+d+1], c1 = g_icos[n*64+d+1];
        Qs[r*65+d]   = (q.x*c0 - q.y*s0)*QSCALE;
        Qs[r*65+d+1] = (q.y*c1 + q.x*s1)*QSCALE;
    }

    // S = Q K^T in 32-key chunks
    for (int jc = 0; jc < 6; jc++) {
        if (jc > 0) __syncthreads();
        for (int p = tid; p < 32*32; p += 256) {
            int r = p >> 5, d = (p & 31) * 2;
            int n = jc*32 + r;
            float2 k = *reinterpret_cast<const float2*>(&g_qkv[tokbase + (size_t)n*(3*DIMM) + DIMM + d]);
            float s0 = g_isin[n*64+d],   c0 = g_icos[n*64+d];
            float s1 = g_isin[n*64+d+1], c1 = g_icos[n*64+d+1];
            KVc[r*65+d]   = k.x*c0 - k.y*s0;
            KVc[r*65+d+1] = k.y*c1 + k.x*s1;
        }
        __syncthreads();
        int i0 = (tid >> 5) * 4, j = tid & 31;
        float a0 = 0.f, a1 = 0.f, a2 = 0.f, a3 = 0.f;
        #pragma unroll 16
        for (int d = 0; d < 64; d++) {
            float kv = KVc[j*65+d];
            a0 = fmaf(Qs[(i0+0)*65+d], kv, a0);
            a1 = fmaf(Qs[(i0+1)*65+d], kv, a1);
            a2 = fmaf(Qs[(i0+2)*65+d], kv, a2);
            a3 = fmaf(Qs[(i0+3)*65+d], kv, a3);
        }
        Ss[(i0+0)*200 + jc*32 + j] = a0;
        Ss[(i0+1)*200 + jc*32 + j] = a1;
        Ss[(i0+2)*200 + jc*32 + j] = a2;
        Ss[(i0+3)*200 + jc*32 + j] = a3;
    }
    __syncthreads();

    // softmax (8 warps x 4 rows)
    {
        int w = tid >> 5, ln = tid & 31;
        #pragma unroll
        for (int rr = 0; rr < 4; rr++) {
            int row = w*4 + rr;
            float v[6];
            float m = -1e30f;
            #pragma unroll
            for (int t = 0; t < 6; t++) { v[t] = Ss[row*200 + ln + t*32]; m = fmaxf(m, v[t]); }
            #pragma unroll
            for (int o = 16; o > 0; o >>= 1) m = fmaxf(m, __shfl_xor_sync(0xffffffffu, m, o));
            float s = 0.f;
            #pragma unroll
            for (int t = 0; t < 6; t++) { v[t] = expf(v[t]-m); s += v[t]; }
            #pragma unroll
            for (int o = 16; o > 0; o >>= 1) s += __shfl_xor_sync(0xffffffffu, s, o);
            float inv = 1.f/s;
            #pragma unroll
            for (int t = 0; t < 6; t++) Ss[row*200 + ln + t*32] = v[t]*inv;
        }
    }

    // O = P V in 32-key chunks
    int r = tid >> 3, c0 = (tid & 7) * 8;
    float o[8] = {0.f,0.f,0.f,0.f,0.f,0.f,0.f,0.f};
    for (int jc = 0; jc < 6; jc++) {
        __syncthreads();
        #pragma unroll
        for (int a = 0; a < 2; a++) {
            int i = tid + a*256;             // 0..511 float4 slots
            int rv = i >> 4, c4 = (i & 15) * 4;
            *reinterpret_cast<float4*>(&KVc[rv*68 + c4]) =
                *reinterpret_cast<const float4*>(&g_qkv[tokbase + (size_t)(jc*32+rv)*(3*DIMM) + 2*DIMM + c4]);
        }
        __syncthreads();
        #pragma unroll
        for (int j = 0; j < 32; j++) {
            float p = Ss[r*200 + jc*32 + j];
            float4 v0 = *reinterpret_cast<const float4*>(&KVc[j*68 + c0]);
            float4 v1 = *reinterpret_cast<const float4*>(&KVc[j*68 + c0 + 4]);
            o[0] = fmaf(p, v0.x, o[0]); o[1] = fmaf(p, v0.y, o[1]);
            o[2] = fmaf(p, v0.z, o[2]); o[3] = fmaf(p, v0.w, o[3]);
            o[4] = fmaf(p, v1.x, o[4]); o[5] = fmaf(p, v1.y, o[5]);
            o[6] = fmaf(p, v1.z, o[6]); o[7] = fmaf(p, v1.w, o[7]);
        }
    }
    int n = qt*32 + r;
    float* dst = &g_attn[((size_t)((b*FFR+f)*NNS + n))*DIMM + h*DHH + c0];
    *reinterpret_cast<float4*>(dst)   = make_float4(o[0], o[1], o[2], o[3]);
    *reinterpret_cast<float4*>(dst+4) = make_float4(o[4], o[5], o[6], o[7]);
}

// ---------------- FFN gate: a * gelu(g), float4 ----------------
__global__ void gate_kernel() {
    int idx = blockIdx.x*blockDim.x + threadIdx.x;
    if (idx >= TT*FFHID/4) return;
    int t = idx / (FFHID/4), j4 = idx % (FFHID/4);
    const float4 a = *reinterpret_cast<const float4*>(&g_h1[(size_t)t*2*FFHID + j4*4]);
    const float4 g = *reinterpret_cast<const float4*>(&g_h1[(size_t)t*2*FFHID + FFHID + j4*4]);
    float4 o;
    o.x = a.x * gelu_f(g.x);
    o.y = a.y * gelu_f(g.y);
    o.z = a.z * gelu_f(g.z);
    o.w = a.w * gelu_f(g.w);
    *reinterpret_cast<float4*>(&g_gate[(size_t)t*FFHID + j4*4]) = o;
}

// ---------------- host orchestration ----------------
extern "C" void kernel_launch(void* const* d_in, const int* in_sizes, int n_in,
                              void* d_out, int out_size) {
    const float* video   = (const float*)d_in[0];
    const float* patch_w = (const float*)d_in[1];
    const float* patch_b = (const float*)d_in[2];
    const float* ln_t_g  = (const float*)d_in[3];
    const float* ln_t_b  = (const float*)d_in[4];
    const float* ln_s_g  = (const float*)d_in[5];
    const float* ln_s_b  = (const float*)d_in[6];
    const float* ln_f_g  = (const float*)d_in[7];
    const float* ln_f_b  = (const float*)d_in[8];
    const float* qkv_t   = (const float*)d_in[9];
    const float* out_t_w = (const float*)d_in[10];
    const float* out_t_b = (const float*)d_in[11];
    const float* qkv_s   = (const float*)d_in[12];
    const float* out_s_w = (const float*)d_in[13];
    const float* out_s_b = (const float*)d_in[14];
    const float* ff_w1   = (const float*)d_in[15];
    const float* ff_b1   = (const float*)d_in[16];
    const float* ff_w2   = (const float*)d_in[17];
    const float* ff_b2   = (const float*)d_in[18];

    float *px, *py, *pqkv, *pattn, *ph1, *pgate, *ppatch;
    cudaGetSymbolAddress((void**)&px,     g_x);
    cudaGetSymbolAddress((void**)&py,     g_y);
    cudaGetSymbolAddress((void**)&pqkv,   g_qkv);
    cudaGetSymbolAddress((void**)&pattn,  g_attn);
    cudaGetSymbolAddress((void**)&ph1,    g_h1);
    cudaGetSymbolAddress((void**)&pgate,  g_gate);
    cudaGetSymbolAddress((void**)&ppatch, g_patch);

    const int SM128 = 3*(128*20 + 16*136)*4;   // 56832 B
    const int SM256 = 3*(128*20 + 16*264)*4;   // 81408 B

    cudaFuncSetAttribute(tgemm<128>, cudaFuncAttributeMaxDynamicSharedMemorySize, SM128);
    cudaFuncSetAttribute(tgemm<256>, cudaFuncAttributeMaxDynamicSharedMemorySize, SM256);

    rope_frame_kernel<<<1, 1024>>>();
    rope_image_kernel<<<(NNS*DHH+255)/256, 256>>>();
    patchify_kernel<<<(TT*PATCH_K+255)/256, 256>>>(video);

    // x = patch @ patch_w + patch_b   (N=512, K=192)
    tgemm<128><<<dim3(DIMM/128, TT/128), 256, SM128>>>(
        ppatch, patch_w, patch_b, nullptr, px, TT, DIMM, PATCH_K, PATCH_K);

    for (int l = 0; l < NDEPTH; l++) {
        // ---- temporal attention ----
        ln_kernel<<<TT, 256>>>(px, ln_t_g + l*DIMM, ln_t_b + l*DIMM, py);
        tgemm<256><<<dim3(3*DIMM/256, TT/128), 256, SM256>>>(
            py, qkv_t + (size_t)l*DIMM*3*DIMM, nullptr, nullptr, pqkv, TT, 3*DIMM, DIMM, DIMM);
        attn_time_kernel<<<dim3(NNS, NHEADS, BB), 256>>>();
        tgemm<128><<<dim3(DIMM/128, TT/128), 256, SM128>>>(
            pattn, out_t_w + (size_t)l*DIMM*DIMM, out_t_b + l*DIMM, px, px, TT, DIMM, DIMM, DIMM);
        // ---- spatial attention ----
        ln_kernel<<<TT, 256>>>(px, ln_s_g + l*DIMM, ln_s_b + l*DIMM, py);
        tgemm<256><<<dim3(3*DIMM/256, TT/128), 256, SM256>>>(
            py, qkv_s + (size_t)l*DIMM*3*DIMM, nullptr, nullptr, pqkv, TT, 3*DIMM, DIMM, DIMM);
        attn_space_kernel<<<dim3(6, BB*NHEADS*FFR), 256>>>();
        tgemm<128><<<dim3(DIMM/128, TT/128), 256, SM128>>>(
            pattn, out_s_w + (size_t)l*DIMM*DIMM, out_s_b + l*DIMM, px, px, TT, DIMM, DIMM, DIMM);
        // ---- FFN ----
        ln_kernel<<<TT, 256>>>(px, ln_f_g + l*DIMM, ln_f_b + l*DIMM, py);
        tgemm<256><<<dim3(2*FFHID/256, TT/128), 256, SM256>>>(
            py, ff_w1 + (size_t)l*DIMM*2*FFHID, ff_b1 + (size_t)l*2*FFHID, nullptr, ph1,
            TT, 2*FFHID, DIMM, DIMM);
        gate_kernel<<<(TT*FFHID/4+255)/256, 256>>>();
        float* cdst = (l == NDEPTH-1) ? (float*)d_out : px;
        tgemm<128><<<dim3(DIMM/128, TT/128), 256, SM128>>>(
            pgate, ff_w2 + (size_t)l*FFHID*DIMM, ff_b2 + l*DIMM, px, cdst,
            TT, DIMM, FFHID, FFHID);
    }
}